// round 11
// baseline (speedup 1.0000x reference)
#include <cuda_runtime.h>
#include <cuda_fp16.h>
#include <stdint.h>

#define TT 256
#define BB 128
#define VV 256
#define EE 512
#define NH 1024
#define TB (TT*BB)          // 32768
#define G4 (4*NH)           // 4096

// ---------------- static device scratch ----------------
__device__ __align__(16) __half g_inph[(size_t)TB*VV];
__device__ __align__(16) __half g_embs[(size_t)TB*EE];
__device__ __align__(16) float  g_X[(size_t)TB*G4];
__device__ __align__(16) __half g_H0[(size_t)TB*NH];    // fragment-permuted layout
__device__ __align__(16) __half g_H1[(size_t)TB*NH];    // fragment-permuted layout
__device__ __align__(16) __half g_embT[EE*VV];           // [512][256]
__device__ __align__(16) __half g_w0xT[(size_t)G4*EE];   // [4096][512]
__device__ __align__(16) __half g_w0hT[(size_t)G4*NH];   // [4096][1024] (unpermuted)
__device__ __align__(16) __half g_w1xT[(size_t)G4*NH];   // [4096][1024] (k-permuted)
__device__ __align__(16) __half g_w1hT[(size_t)G4*NH];   // [4096][1024] (unpermuted)
__device__ __align__(16) __half g_owT[VV*NH];            // [256][1024]  (k-permuted)
__device__ int g_ctr[2];

// fragment permutation within 16-col blocks: logical col c -> phys (c&~15)+perm(c&15)
__device__ __forceinline__ int permk(int k) {
    int i = k & 15;
    return (k & ~15) | ((((i >> 1) & 3) << 2) | (((i >> 3) & 1) << 1) | (i & 1));
}

// ---------------- helpers ----------------
__device__ __forceinline__ void mma16(float d[4], const unsigned a[4], const unsigned b[2]) {
    asm volatile(
        "mma.sync.aligned.m16n8k16.row.col.f32.f16.f16.f32 "
        "{%0,%1,%2,%3}, {%4,%5,%6,%7}, {%8,%9}, {%0,%1,%2,%3};\n"
        : "+f"(d[0]), "+f"(d[1]), "+f"(d[2]), "+f"(d[3])
        : "r"(a[0]), "r"(a[1]), "r"(a[2]), "r"(a[3]), "r"(b[0]), "r"(b[1]));
}
__device__ __forceinline__ void ldsm_x4(unsigned r[4], const __half* p) {
    unsigned a = (unsigned)__cvta_generic_to_shared(p);
    asm volatile("ldmatrix.sync.aligned.m8n8.x4.shared.b16 {%0,%1,%2,%3}, [%4];\n"
        : "=r"(r[0]), "=r"(r[1]), "=r"(r[2]), "=r"(r[3]) : "r"(a));
}
__device__ __forceinline__ void cpa16(__half* dst, const __half* src) {
    unsigned d = (unsigned)__cvta_generic_to_shared(dst);
    asm volatile("cp.async.cg.shared.global [%0], [%1], 16;\n" :: "r"(d), "l"(src));
}
#define CPA_COMMIT() asm volatile("cp.async.commit_group;\n" ::: "memory")
template <int N> __device__ __forceinline__ void cpa_wait() {
    asm volatile("cp.async.wait_group %0;\n" :: "n"(N) : "memory");
}
#define LDG64CG(d, p) asm volatile("ld.global.cg.v2.u32 {%0,%1}, [%2];" \
    : "=r"((d).x), "=r"((d).y) : "l"(p))
__device__ __forceinline__ void cstore2(float* C, size_t i, float a, float b) {
    *(float2*)&C[i] = make_float2(a, b);
}
__device__ __forceinline__ void cstore2(__half* C, size_t i, float a, float b) {
    *(__half2*)&C[i] = __floats2half2_rn(a, b);
}
__device__ __forceinline__ float sigf(float x) { return 1.f / (1.f + __expf(-x)); }

__global__ void zero_i(int* p) { if (threadIdx.x < 2) p[threadIdx.x] = 0; }
__global__ void f2h_kernel(const float* __restrict__ s, __half* __restrict__ d, int n) {
    for (int i = blockIdx.x * blockDim.x + threadIdx.x; i < n; i += gridDim.x * blockDim.x)
        d[i] = __float2half(s[i]);
}
// src fp32 [K][N] (row stride lds) -> dst fp16 [N][K]; PERM: k-index fragment-permuted
template <bool PERM>
__global__ void transpose_cvt(const float* __restrict__ src, int lds,
                              __half* __restrict__ dst, int K, int N) {
    __shared__ float tile[32][33];
    int kb = blockIdx.x * 32, nb = blockIdx.y * 32;
    #pragma unroll
    for (int i = threadIdx.y; i < 32; i += 8) {
        int k = kb + i, n = nb + threadIdx.x;
        tile[i][threadIdx.x] = (k < K && n < N) ? src[(size_t)k * lds + n] : 0.f;
    }
    __syncthreads();
    #pragma unroll
    for (int i = threadIdx.y; i < 32; i += 8) {
        int n = nb + i, k = kb + threadIdx.x;
        if (n < N && k < K) {
            int kd = PERM ? permk(k) : k;
            dst[(size_t)n * K + kd] = __float2half(tile[threadIdx.x][i]);
        }
    }
}

// ---------------- fp16 GEMM (validated R7): C = A @ Bt^T (+bias), 128x128 tile ----------------
#define GAST (128*40)
#define GBST (128*40)
#define GEMM_SMEM ((4*(GAST+GBST))*2)

template <typename TOUT>
__global__ void __launch_bounds__(256, 2) gemm16(
    const __half* __restrict__ A, int lda,
    const __half* __restrict__ Bt,
    TOUT* __restrict__ C, int ldc,
    const float* __restrict__ bias,
    int M, int N, int K)
{
    extern __shared__ __half sm[];
    __half* As = sm;
    __half* Bs = sm + 4*GAST;

    const int tid = threadIdx.x;
    const int bm = blockIdx.y * 128, bn = blockIdx.x * 128;
    const int wid = tid >> 5, lane = tid & 31;
    const int wr = (wid & 1) * 64, wc = (wid >> 1) * 32;
    const int r = lane >> 2, cl = lane & 3;

    float acc[4][4][4];
    #pragma unroll
    for (int i = 0; i < 4; ++i)
        #pragma unroll
        for (int j = 0; j < 4; ++j)
            #pragma unroll
            for (int k = 0; k < 4; ++k) acc[i][j][k] = 0.f;

    auto loadG = [&](int s, int kt) {
        #pragma unroll
        for (int i = 0; i < 2; ++i) {
            int idx = tid + i * 256;
            int row = idx >> 2, cc = idx & 3;
            cpa16(As + s*GAST + row*40 + cc*8,
                  A + (size_t)(bm + row) * lda + kt*32 + cc*8);
            cpa16(Bs + s*GBST + row*40 + cc*8,
                  Bt + (size_t)(bn + row) * K + kt*32 + cc*8);
        }
    };

    const int ktiles = K >> 5;
    #pragma unroll
    for (int s = 0; s < 3; ++s) { if (s < ktiles) loadG(s, s); CPA_COMMIT(); }

    const int a_row = (lane & 15);
    const int a_col = (lane >> 4) << 3;
    const int b_row = (lane & 7) + ((lane >> 4) << 3);
    const int b_col = (lane & 8);

    for (int kt = 0; kt < ktiles; ++kt) {
        cpa_wait<2>();
        __syncthreads();
        if (kt + 3 < ktiles) loadG((kt + 3) & 3, kt + 3);
        CPA_COMMIT();

        const __half* sA = As + (kt & 3) * GAST;
        const __half* sB = Bs + (kt & 3) * GBST;
        #pragma unroll
        for (int ks = 0; ks < 2; ++ks) {
            const int k0 = ks * 16;
            unsigned af[4][4], bf01[4], bf23[4];
            #pragma unroll
            for (int mt = 0; mt < 4; ++mt)
                ldsm_x4(af[mt], sA + (wr + mt*16 + a_row)*40 + k0 + a_col);
            ldsm_x4(bf01, sB + (wc      + b_row)*40 + k0 + b_col);
            ldsm_x4(bf23, sB + (wc + 16 + b_row)*40 + k0 + b_col);
            #pragma unroll
            for (int mt = 0; mt < 4; ++mt) {
                mma16(acc[mt][0], af[mt], bf01 + 0);
                mma16(acc[mt][1], af[mt], bf01 + 2);
                mma16(acc[mt][2], af[mt], bf23 + 0);
                mma16(acc[mt][3], af[mt], bf23 + 2);
            }
        }
    }

    #pragma unroll
    for (int mt = 0; mt < 4; ++mt)
        #pragma unroll
        for (int nt = 0; nt < 4; ++nt) {
            const int row = bm + wr + mt*16 + r;
            const int col = bn + wc + nt*8 + 2*cl;
            const float b0 = bias ? bias[col]     : 0.f;
            const float b1 = bias ? bias[col + 1] : 0.f;
            cstore2(C, (size_t)row * ldc + col,       acc[mt][nt][0] + b0, acc[mt][nt][1] + b1);
            cstore2(C, (size_t)(row + 8) * ldc + col, acc[mt][nt][2] + b0, acc[mt][nt][3] + b1);
        }
}

// ---------------- persistent LSTM layer kernel ----------------
// 128 CTAs (1/SM). CTA bx owns hidden cols [bx*8, bx*8+8) of all 4 gates
// (GEMM N=32, K=1024). W_h slice (64KB) resident in smem (unpermuted).
// A (h, fragment-permuted in global) loaded DIRECTLY global->registers via
// LDG.64.cg with a 16-deep register ring: no A smem staging, no k-loop barriers.
// Sync: counter + release-reduction + backoff acquire spin.
#define BST  (32*1032)
#define XS_OFF (BST*2)                       // byte offset of X stage (fp32 [128][36])
#define LSTM_SMEM (XS_OFF + 128*36*4)

__global__ void __launch_bounds__(256, 1) lstm_layer(
    const __half* __restrict__ WhT,    // [4096][1024] unpermuted
    const float*  __restrict__ X,      // [T*128][4096]
    __half* __restrict__ H,            // [T*128][1024] fragment-permuted
    int* __restrict__ ctr)
{
    extern __shared__ __half sm[];
    __half* Bs = sm;                   // 32 x 1032 (n = gate*8+j, k = 0..1023)
    float*  Xs = (float*)((char*)sm + XS_OFF);   // 128 x 36 fp32

    const int tid = threadIdx.x, lane = tid & 31, wid = tid >> 5;
    const int r = lane >> 2, cl = lane & 3;
    const int bx = blockIdx.x;
    const int wr = wid * 16;
    const int row0 = wr + r, row1 = row0 + 8;
    const int jj = 2 * cl;
    const int colg = bx * 8 + jj;
    // physical (permuted) column this thread's h-pair lands at
    const int colp = (colg & ~15) + cl * 4 + (bx & 1) * 2;

    // load W_h slice once: rows g*1024 + bx*8 + j  ->  Bs[g*8+j][0..1023]
    #pragma unroll
    for (int i = 0; i < 16; ++i) {
        int idx = tid + i * 256;            // 0..4095
        int n = idx >> 7, cc = idx & 127;
        int g = n >> 3, j = n & 7;
        cpa16(Bs + n*1032 + cc*8,
              WhT + (size_t)(g*1024 + bx*8 + j) * 1024 + cc*8);
    }
    CPA_COMMIT();
    cpa_wait<0>();
    __syncthreads();

    float c0 = 0.f, c1 = 0.f, c2 = 0.f, c3 = 0.f;

    // stage this step's X gate block [128 rows][4 gates x 8 cols] into smem
    auto loadX = [&](const float* Xt) {
        #pragma unroll
        for (int i = 0; i < 4; ++i) {
            int u = tid + i * 256;          // 0..1023 (16B granules)
            int row = u >> 3, seg = u & 7;  // seg = gate*2 + half
            int g = seg >> 1, hf = seg & 1;
            cpa16((__half*)(Xs + row*36 + g*8 + hf*4),
                  (const __half*)(Xt + (size_t)row*4096 + g*1024 + bx*8 + hf*4));
        }
    };

    for (int t = 0; t < TT; ++t) {
        float acc[4][4];
        #pragma unroll
        for (int i = 0; i < 4; ++i)
            #pragma unroll
            for (int j = 0; j < 4; ++j) acc[i][j] = 0.f;

        const float* Xt = X + (size_t)t * (BB * G4);
        loadX(Xt); CPA_COMMIT();

        if (t > 0) {
            const __half* hsrc = H + (size_t)(t - 1) * BB * NH;
            const __half* p0 = hsrc + (size_t)row0 * 1024 + cl * 4;
            const __half* p1 = hsrc + (size_t)row1 * 1024 + cl * 4;

            // register ring: 16 ks-slices in flight
            uint2 alo[16], ahi[16];
            #pragma unroll
            for (int s = 0; s < 16; ++s) {
                LDG64CG(alo[s], p0 + s * 16);
                LDG64CG(ahi[s], p1 + s * 16);
            }

            auto group = [&](int kb, int base) {   // base must be a literal (0 or 8)
                const bool pf = (kb < 6);
                const __half* q0 = p0 + (kb + 2) * 128;
                const __half* q1 = p1 + (kb + 2) * 128;
                const int ksb = kb * 8;
                #pragma unroll
                for (int u = 0; u < 8; ++u) {
                    unsigned af[4] = { alo[base+u].x, ahi[base+u].x,
                                       alo[base+u].y, ahi[base+u].y };
                    if (pf) { LDG64CG(alo[base+u], q0 + u * 16);
                              LDG64CG(ahi[base+u], q1 + u * 16); }
                    const int ks = ksb + u;
                    #pragma unroll
                    for (int nt = 0; nt < 4; ++nt) {
                        const __half* bp = Bs + (size_t)(nt*8 + r)*1032 + ks*16 + jj;
                        unsigned bf[2];
                        bf[0] = *(const unsigned*)bp;
                        bf[1] = *(const unsigned*)(bp + 8);
                        mma16(acc[nt], af, bf);
                    }
                }
            };
            #pragma unroll 1
            for (int kbp = 0; kbp < 4; ++kbp) {
                group(2*kbp,     0);
                group(2*kbp + 1, 8);
            }
        }

        cpa_wait<0>();     // Xs staged
        __syncthreads();   // Xs visible to all

        // gates + state update, all in registers (X from smem stage)
        {
            const float* xa = Xs + row0*36 + jj;
            float2 xf = *(const float2*)(xa);
            float2 xi = *(const float2*)(xa + 8);
            float2 xo = *(const float2*)(xa + 16);
            float2 xg = *(const float2*)(xa + 24);
            float f  = sigf(acc[0][0] + xf.x), ig  = sigf(acc[1][0] + xi.x);
            float o  = sigf(acc[2][0] + xo.x), gg  = tanhf(acc[3][0] + xg.x);
            c0 = f * c0 + ig * gg;
            float f1 = sigf(acc[0][1] + xf.y), ig1 = sigf(acc[1][1] + xi.y);
            float o1 = sigf(acc[2][1] + xo.y), gg1 = tanhf(acc[3][1] + xg.y);
            c1 = f1 * c1 + ig1 * gg1;
            __half2 hv = __floats2half2_rn(o * tanhf(c0), o1 * tanhf(c1));
            *(__half2*)&H[(size_t)t*BB*NH + (size_t)row0*1024 + colp] = hv;
        }
        {
            const float* xb = Xs + row1*36 + jj;
            float2 xf = *(const float2*)(xb);
            float2 xi = *(const float2*)(xb + 8);
            float2 xo = *(const float2*)(xb + 16);
            float2 xg = *(const float2*)(xb + 24);
            float f  = sigf(acc[0][2] + xf.x), ig  = sigf(acc[1][2] + xi.x);
            float o  = sigf(acc[2][2] + xo.x), gg  = tanhf(acc[3][2] + xg.x);
            c2 = f * c2 + ig * gg;
            float f1 = sigf(acc[0][3] + xf.y), ig1 = sigf(acc[1][3] + xi.y);
            float o1 = sigf(acc[2][3] + xo.y), gg1 = tanhf(acc[3][3] + xg.y);
            c3 = f1 * c3 + ig1 * gg1;
            __half2 hv = __floats2half2_rn(o * tanhf(c2), o1 * tanhf(c3));
            *(__half2*)&H[(size_t)t*BB*NH + (size_t)row1*1024 + colp] = hv;
        }

        if (t + 1 < TT) {
            __syncthreads();       // all CTA threads' H stores happen-before tid0's release
            if (tid == 0) {
                asm volatile("red.release.gpu.global.add.u32 [%0], %1;"
                             :: "l"(ctr), "r"(1) : "memory");
                const int target = 128 * (t + 1);
                int v;
                while (true) {
                    asm volatile("ld.acquire.gpu.b32 %0, [%1];" : "=r"(v) : "l"(ctr));
                    if (v >= target) break;
                    __nanosleep(64);   // backoff
                }
            }
            __syncthreads();       // broadcast acquire to whole CTA
        }
    }
}

// ---------------- launch ----------------
extern "C" void kernel_launch(void* const* d_in, const int* in_sizes, int n_in,
                              void* d_out, int out_size) {
    (void)in_sizes; (void)n_in; (void)out_size;
    const float* inputs = (const float*)d_in[0];
    const float* emb    = (const float*)d_in[1];
    const float* w0     = (const float*)d_in[2];
    const float* b0     = (const float*)d_in[3];
    const float* w1     = (const float*)d_in[4];
    const float* b1     = (const float*)d_in[5];
    const float* outw   = (const float*)d_in[6];
    const float* outb   = (const float*)d_in[7];
    float* out = (float*)d_out;

    __half *inph, *embs, *H0, *H1, *embT, *w0xT, *w0hT, *w1xT, *w1hT, *owT;
    float *X;
    int *ctr;
    cudaGetSymbolAddress((void**)&inph, g_inph);
    cudaGetSymbolAddress((void**)&embs, g_embs);
    cudaGetSymbolAddress((void**)&X,    g_X);
    cudaGetSymbolAddress((void**)&H0,   g_H0);
    cudaGetSymbolAddress((void**)&H1,   g_H1);
    cudaGetSymbolAddress((void**)&embT, g_embT);
    cudaGetSymbolAddress((void**)&w0xT, g_w0xT);
    cudaGetSymbolAddress((void**)&w0hT, g_w0hT);
    cudaGetSymbolAddress((void**)&w1xT, g_w1xT);
    cudaGetSymbolAddress((void**)&w1hT, g_w1hT);
    cudaGetSymbolAddress((void**)&owT,  g_owT);
    cudaGetSymbolAddress((void**)&ctr,  g_ctr);

    cudaFuncSetAttribute(lstm_layer,     cudaFuncAttributeMaxDynamicSharedMemorySize, LSTM_SMEM);
    cudaFuncSetAttribute(gemm16<float>,  cudaFuncAttributeMaxDynamicSharedMemorySize, GEMM_SMEM);
    cudaFuncSetAttribute(gemm16<__half>, cudaFuncAttributeMaxDynamicSharedMemorySize, GEMM_SMEM);

    // prep
    f2h_kernel<<<1024, 256>>>(inputs, inph, TB * VV);
    {
        dim3 blk(32, 8);
        transpose_cvt<false><<<dim3(VV/32, EE/32), blk>>>(emb,                EE, embT, VV, EE);
        transpose_cvt<false><<<dim3(EE/32, G4/32), blk>>>(w0,                 G4, w0xT, EE, G4);
        transpose_cvt<false><<<dim3(NH/32, G4/32), blk>>>(w0 + (size_t)EE*G4, G4, w0hT, NH, G4);
        // k-permuted: consumed with fragment-permuted H as A
        transpose_cvt<true ><<<dim3(NH/32, G4/32), blk>>>(w1,                 G4, w1xT, NH, G4);
        transpose_cvt<false><<<dim3(NH/32, G4/32), blk>>>(w1 + (size_t)NH*G4, G4, w1hT, NH, G4);
        transpose_cvt<true ><<<dim3(NH/32, VV/32), blk>>>(outw,               VV, owT,  NH, VV);
    }
    zero_i<<<1, 32>>>(ctr);

    // embs = inputs @ emb
    gemm16<__half><<<dim3(EE/128, TB/128), 256, GEMM_SMEM>>>(inph, VV, embT, embs, EE, nullptr, TB, EE, VV);
    // X = embs @ W0x + b0
    gemm16<float><<<dim3(G4/128, TB/128), 256, GEMM_SMEM>>>(embs, EE, w0xT, X, G4, b0, TB, G4, EE);
    // layer 0 (persistent)
    lstm_layer<<<128, 256, LSTM_SMEM>>>(w0hT, X, H0, ctr);
    // X = H0 @ W1x + b1   (H0 permuted, w1xT k-permuted -> consistent)
    gemm16<float><<<dim3(G4/128, TB/128), 256, GEMM_SMEM>>>(H0, NH, w1xT, X, G4, b1, TB, G4, NH);
    // layer 1 (persistent)
    lstm_layer<<<128, 256, LSTM_SMEM>>>(w1hT, X, H1, ctr + 1);
    // logits = H1 @ out_w + out_b   (H1 permuted, owT k-permuted)
    gemm16<float><<<dim3(VV/128, TB/128), 256, GEMM_SMEM>>>(H1, NH, owT, out, VV, outb, TB, VV, NH);
}